// round 14
// baseline (speedup 1.0000x reference)
#include <cuda_runtime.h>
#include <cstdint>

// ---------------------------------------------------------------------------
// Problem constants (fixed by the reference)
// ---------------------------------------------------------------------------
#define B_GRAPHS 64      // graphs in batch
#define D 128            // D_NODE == D_REG
#define H1DIM 256        // hidden
#define H2DIM 128        // hidden/2
#define PNUM 64          // partitions
#define TM 64            // boundary rows per block in main kernel

// ---------------------------------------------------------------------------
// Device scratch (no allocations allowed -> __device__ globals)
// ---------------------------------------------------------------------------
__device__ float g_sums[B_GRAPHS * D];
__device__ float g_cnt[B_GRAPHS];
__device__ float g_contrib_ns[B_GRAPHS * H1DIM];  // gc part of layer1 + b1 folded in
__device__ float g_contrib_ps[B_GRAPHS * H1DIM];
__device__ int   g_mask_kind;                     // 0=byte, 1=int32, 2=float32

// ---------------------------------------------------------------------------
// Kernel 0: zero the segment accumulators (graph replay must be deterministic)
// ---------------------------------------------------------------------------
__global__ void k_zero() {
    int t = blockIdx.x * blockDim.x + threadIdx.x;
    if (t < B_GRAPHS * D) g_sums[t] = 0.f;
    if (t < B_GRAPHS)     g_cnt[t]  = 0.f;
}

// ---------------------------------------------------------------------------
// Kernel 1: segment-sum of region embeddings + counts
// ---------------------------------------------------------------------------
__global__ void k_segsum(const float* __restrict__ re,
                         const int* __restrict__ rb, int R) {
    int idx = blockIdx.x * blockDim.x + threadIdx.x;
    int total = R * D;
    if (idx < total) {
        int r = idx >> 7;          // / D
        int d = idx & (D - 1);
        atomicAdd(&g_sums[rb[r] * D + d], re[idx]);
    }
    if (idx < R) atomicAdd(&g_cnt[rb[idx]], 1.f);
}

// ---------------------------------------------------------------------------
// Kernel 2: detect action_mask storage dtype (bool is not a harness dtype).
// Deterministic: depends only on input bytes.
// ---------------------------------------------------------------------------
__global__ void k_detect(const unsigned int* __restrict__ w, int nwords) {
    __shared__ int not_int, not_float;
    if (threadIdx.x == 0) { not_int = 0; not_float = 0; }
    __syncthreads();
    int li = 0, lf = 0;
    for (int i = threadIdx.x; i < nwords; i += blockDim.x) {
        unsigned v = w[i];
        if (v > 1u) li = 1;                           // not plausible int32 bool
        if (v != 0u && v != 0x3f800000u) lf = 1;      // not plausible f32 bool
    }
    if (li) not_int = 1;
    if (lf) not_float = 1;
    __syncthreads();
    if (threadIdx.x == 0)
        g_mask_kind = not_int ? (not_float ? 0 : 2) : 1;
}

// ---------------------------------------------------------------------------
// Kernel 3: per-batch global context MLP + per-batch layer-1 contribution
//   mean   = sums/max(cnt,1)                              [64,128]
//   gc     = relu(mean@ge_w1+ge_b1)@ge_w2+ge_b2           [64,128]
//   contrib_h[b][j] = sum_k gc[b][k]*h_w1[128+k][j] + h_b1[j]   (both heads)
// One block per batch, 256 threads.
// ---------------------------------------------------------------------------
__global__ void k_global(const float* __restrict__ ge_w1, const float* __restrict__ ge_b1,
                         const float* __restrict__ ge_w2, const float* __restrict__ ge_b2,
                         const float* __restrict__ ns_w1, const float* __restrict__ ns_b1,
                         const float* __restrict__ ps_w1, const float* __restrict__ ps_b1) {
    __shared__ float mean[D], h[H1DIM], gc[D];
    int b = blockIdx.x, t = threadIdx.x;
    if (t < D) mean[t] = g_sums[b * D + t] / fmaxf(g_cnt[b], 1.f);
    __syncthreads();
    {
        float a = ge_b1[t];
        #pragma unroll 4
        for (int k = 0; k < D; ++k) a = fmaf(mean[k], ge_w1[k * H1DIM + t], a);
        h[t] = fmaxf(a, 0.f);
    }
    __syncthreads();
    if (t < D) {
        float a = ge_b2[t];
        #pragma unroll 4
        for (int j = 0; j < H1DIM; ++j) a = fmaf(h[j], ge_w2[j * D + t], a);
        gc[t] = a;
    }
    __syncthreads();
    {
        float cn = ns_b1[t], cp = ps_b1[t];
        #pragma unroll 4
        for (int k = 0; k < D; ++k) {
            float g = gc[k];
            cn = fmaf(g, ns_w1[(D + k) * H1DIM + t], cn);
            cp = fmaf(g, ps_w1[(D + k) * H1DIM + t], cp);
        }
        g_contrib_ns[b * H1DIM + t] = cn;
        g_contrib_ps[b * H1DIM + t] = cp;
    }
}

// ---------------------------------------------------------------------------
// Main fused kernel: per 64 boundary rows, run both 3-layer MLP heads.
// 256 threads, register-blocked FFMA GEMMs, weights staged through smem.
//
// Dynamic smem layout (floats):
//   xs : [64][132]      node-embedding half of the input   (offset 0,    8448)
//   h1 : [64][256]      layer-1 activations / ps_w3 stage  (offset 8448, 16384)
//   h2 : [64][132]      layer-2 activations                (offset 24832, 8448)
//   wt : [4096]         weight tile staging                (offset 33280, 4096)
//   nid/bid : 128 ints                                     (offset 37376)
// total = 37504 floats = 150016 bytes
// ---------------------------------------------------------------------------
#define SM_XS 0
#define SM_H1 8448
#define SM_H2 24832
#define SM_WT 33280
#define SM_ID 37376
#define SMEM_BYTES 150016

__global__ __launch_bounds__(256) void k_main(
    const float* __restrict__ node_emb,
    const int*   __restrict__ boundary,
    const int*   __restrict__ nbidx,
    const void*  __restrict__ amask,
    const float* __restrict__ ns_w1, const float* __restrict__ ns_w2,
    const float* __restrict__ ns_b2, const float* __restrict__ ns_w3,
    const float* __restrict__ ns_b3,
    const float* __restrict__ ps_w1, const float* __restrict__ ps_w2,
    const float* __restrict__ ps_b2, const float* __restrict__ ps_w3,
    const float* __restrict__ ps_b3,
    float* __restrict__ out_node, float* __restrict__ out_part,
    int NB)
{
    extern __shared__ float sm[];
    float* xs = sm + SM_XS;     // row stride 132
    float* h1 = sm + SM_H1;     // row stride 256
    float* h2 = sm + SM_H2;     // row stride 132
    float* wt = sm + SM_WT;
    int*  nid = (int*)(sm + SM_ID);
    int*  bid = nid + TM;

    const int tid = threadIdx.x;
    const int cg  = tid & 31;   // lane -> column group
    const int rg  = tid >> 5;   // warp -> row group
    const int rb0 = rg * 8;
    const int base = blockIdx.x * TM;

    // --- gather row indices + batch indices ---
    if (tid < TM) {
        int row = base + tid;
        int n = boundary[row < NB ? row : (NB - 1)];
        nid[tid] = n;
        bid[tid] = nbidx[n];
    }
    __syncthreads();

    // --- gather node embeddings into xs (warp r loads row r, float4) ---
    for (int r = rg; r < TM; r += 8) {
        const float4* src = (const float4*)(node_emb + (size_t)nid[r] * D);
        ((float4*)(xs + r * 132))[cg] = src[cg];
    }
    __syncthreads();

    for (int head = 0; head < 2; ++head) {
        const float* w1      = head ? ps_w1 : ns_w1;
        const float* contrib = head ? g_contrib_ps : g_contrib_ns;
        const float* w2      = head ? ps_w2 : ns_w2;
        const float* b2      = head ? ps_b2 : ns_b2;

        // ---------------- layer 1: [64,128] x [128,256] ----------------
        float acc[8][8];
        #pragma unroll
        for (int j = 0; j < 8; ++j)
            #pragma unroll
            for (int i = 0; i < 8; ++i) acc[j][i] = 0.f;

        for (int k0 = 0; k0 < D; k0 += 16) {
            __syncthreads();
            #pragma unroll
            for (int it = 0; it < 16; ++it) {
                int idx = tid + it * 256;
                wt[idx] = w1[(k0 + (idx >> 8)) * H1DIM + (idx & 255)];
            }
            __syncthreads();
            #pragma unroll
            for (int kk = 0; kk < 16; ++kk) {
                float xr[8], wf[8];
                #pragma unroll
                for (int j = 0; j < 8; ++j) xr[j] = xs[(rb0 + j) * 132 + k0 + kk];
                #pragma unroll
                for (int i = 0; i < 8; ++i) wf[i] = wt[kk * 256 + cg + 32 * i];
                #pragma unroll
                for (int j = 0; j < 8; ++j)
                    #pragma unroll
                    for (int i = 0; i < 8; ++i)
                        acc[j][i] = fmaf(xr[j], wf[i], acc[j][i]);
            }
        }
        __syncthreads();
        #pragma unroll
        for (int j = 0; j < 8; ++j) {
            int row = rb0 + j;
            const float* cb = contrib + bid[row] * H1DIM;
            #pragma unroll
            for (int i = 0; i < 8; ++i) {
                int c = cg + 32 * i;
                h1[row * 256 + c] = fmaxf(acc[j][i] + cb[c], 0.f);
            }
        }
        __syncthreads();

        // ---------------- layer 2: [64,256] x [256,128] ----------------
        float a2[8][4];
        #pragma unroll
        for (int j = 0; j < 8; ++j)
            #pragma unroll
            for (int i = 0; i < 4; ++i) a2[j][i] = 0.f;

        for (int k0 = 0; k0 < H1DIM; k0 += 16) {
            __syncthreads();
            #pragma unroll
            for (int it = 0; it < 8; ++it) {
                int idx = tid + it * 256;
                wt[idx] = w2[(k0 + (idx >> 7)) * H2DIM + (idx & 127)];
            }
            __syncthreads();
            #pragma unroll
            for (int kk = 0; kk < 16; ++kk) {
                float xr[8], wf[4];
                #pragma unroll
                for (int j = 0; j < 8; ++j) xr[j] = h1[(rb0 + j) * 256 + k0 + kk];
                #pragma unroll
                for (int i = 0; i < 4; ++i) wf[i] = wt[kk * 128 + cg + 32 * i];
                #pragma unroll
                for (int j = 0; j < 8; ++j)
                    #pragma unroll
                    for (int i = 0; i < 4; ++i)
                        a2[j][i] = fmaf(xr[j], wf[i], a2[j][i]);
            }
        }
        __syncthreads();
        #pragma unroll
        for (int j = 0; j < 8; ++j) {
            int row = rb0 + j;
            #pragma unroll
            for (int i = 0; i < 4; ++i) {
                int c = cg + 32 * i;
                h2[row * 132 + c] = fmaxf(a2[j][i] + b2[c], 0.f);
            }
        }
        __syncthreads();

        // ---------------- layer 3 ----------------
        if (head == 0) {
            // node logits: [64,128] x [128,1]
            if (tid < TM) {
                float s = ns_b3[0];
                const float* hr = h2 + tid * 132;
                #pragma unroll 4
                for (int d2 = 0; d2 < H2DIM; ++d2) s = fmaf(hr[d2], ns_w3[d2], s);
                int row = base + tid;
                if (row < NB) out_node[row] = s;
            }
            // next head begins with __syncthreads() before touching h1/h2
        } else {
            // partition logits: [64,128] x [128,64] + mask
            float* w3s = h1;   // h1 is dead now; reuse as ps_w3 stage (8192 floats)
            __syncthreads();
            #pragma unroll
            for (int it = 0; it < 32; ++it)
                w3s[tid + it * 256] = ps_w3[tid + it * 256];
            __syncthreads();

            float a3[8][2];
            #pragma unroll
            for (int j = 0; j < 8; ++j) { a3[j][0] = 0.f; a3[j][1] = 0.f; }
            #pragma unroll 4
            for (int d2 = 0; d2 < H2DIM; ++d2) {
                float w0 = w3s[d2 * PNUM + cg];
                float w1v = w3s[d2 * PNUM + cg + 32];
                #pragma unroll
                for (int j = 0; j < 8; ++j) {
                    float x = h2[(rb0 + j) * 132 + d2];
                    a3[j][0] = fmaf(x, w0, a3[j][0]);
                    a3[j][1] = fmaf(x, w1v, a3[j][1]);
                }
            }
            int kind = g_mask_kind;
            #pragma unroll
            for (int j = 0; j < 8; ++j) {
                int row  = rb0 + j;
                int grow = base + row;
                if (grow >= NB) continue;
                size_t n = (size_t)nid[row];
                #pragma unroll
                for (int i = 0; i < 2; ++i) {
                    int p = cg + 32 * i;
                    float v = a3[j][i] + ps_b3[p];
                    size_t off = n * PNUM + p;
                    bool m;
                    if (kind == 0)      m = ((const unsigned char*)amask)[off] != 0;
                    else if (kind == 1) m = ((const int*)amask)[off] != 0;
                    else                m = ((const float*)amask)[off] != 0.f;
                    out_part[(size_t)grow * PNUM + p] = m ? v : -1e9f;
                }
            }
        }
    }
}

// ---------------------------------------------------------------------------
// Launcher
// ---------------------------------------------------------------------------
extern "C" void kernel_launch(void* const* d_in, const int* in_sizes, int n_in,
                              void* d_out, int out_size) {
    const float* node_emb   = (const float*)d_in[0];
    const float* region_emb = (const float*)d_in[1];
    const int*   boundary   = (const int*)d_in[2];
    const int*   nbidx      = (const int*)d_in[3];
    const int*   rbidx      = (const int*)d_in[4];
    const void*  amask      = d_in[5];
    const float* ge_w1 = (const float*)d_in[6];
    const float* ge_b1 = (const float*)d_in[7];
    const float* ge_w2 = (const float*)d_in[8];
    const float* ge_b2 = (const float*)d_in[9];
    const float* ns_w1 = (const float*)d_in[10];
    const float* ns_b1 = (const float*)d_in[11];
    const float* ns_w2 = (const float*)d_in[12];
    const float* ns_b2 = (const float*)d_in[13];
    const float* ns_w3 = (const float*)d_in[14];
    const float* ns_b3 = (const float*)d_in[15];
    const float* ps_w1 = (const float*)d_in[16];
    const float* ps_b1 = (const float*)d_in[17];
    const float* ps_w2 = (const float*)d_in[18];
    const float* ps_b2 = (const float*)d_in[19];
    const float* ps_w3 = (const float*)d_in[20];
    const float* ps_b3 = (const float*)d_in[21];

    const int NB = in_sizes[2];
    const int R  = in_sizes[4];
    const int maskElems = in_sizes[5];

    float* out_node = (float*)d_out;
    float* out_part = out_node + NB;

    // idempotent; legal during graph capture (not a stream operation)
    cudaFuncSetAttribute(k_main, cudaFuncAttributeMaxDynamicSharedMemorySize,
                         SMEM_BYTES);

    k_zero<<<(B_GRAPHS * D + 255) / 256, 256>>>();
    k_segsum<<<(R * D + 255) / 256, 256>>>(region_emb, rbidx, R);

    int nwords = maskElems / 4;          // safe lower bound on buffer words
    if (nwords > 65536) nwords = 65536;
    k_detect<<<1, 256>>>((const unsigned int*)amask, nwords);

    k_global<<<B_GRAPHS, 256>>>(ge_w1, ge_b1, ge_w2, ge_b2,
                                ns_w1, ns_b1, ps_w1, ps_b1);

    int grid = (NB + TM - 1) / TM;
    k_main<<<grid, 256, SMEM_BYTES>>>(node_emb, boundary, nbidx, amask,
                                      ns_w1, ns_w2, ns_b2, ns_w3, ns_b3,
                                      ps_w1, ps_w2, ps_b2, ps_w3, ps_b3,
                                      out_node, out_part, NB);
}

// round 16
// speedup vs baseline: 2.5224x; 2.5224x over previous
#include <cuda_runtime.h>
#include <cuda_bf16.h>
#include <cstdint>

// ---------------------------------------------------------------------------
// Problem constants
// ---------------------------------------------------------------------------
#define B_GRAPHS 64
#define D 128
#define H1DIM 256
#define H2DIM 128
#define PNUM 64

// SMEM byte offsets (dynamic smem)
#define SM_AHI 0          // X / h2 hi pairs: [128][68] uint32 = 34816 B
#define SM_ALO 34816      // X / h2 lo pairs
#define SM_B1  69632      // B-L1 stage (131072 B) / h1 / B-L3
#define SM_H1HI 69632     // h1 hi pairs: [128][132] uint32 = 67584 B
#define SM_H1LO 137216    // h1 lo pairs
#define SM_MISC 204800
#define SMEM_BYTES 207616
#define STRA 68           // uint32 stride for K=128 pair images
#define STRH 132          // uint32 stride for K=256 pair images

// ---------------------------------------------------------------------------
// Device scratch
// ---------------------------------------------------------------------------
__device__ float g_sums[B_GRAPHS * D];
__device__ float g_cnt[B_GRAPHS];
__device__ float g_contrib_ns[B_GRAPHS * H1DIM];
__device__ float g_contrib_ps[B_GRAPHS * H1DIM];
__device__ int   g_mask_kind;

// Pre-built B fragments in m16n8k16 register order (bf16x2 per uint32).
// w1: [head] flat = nh*16384 + term*8192 + nt*512 + kt*64 + lane*2 + reg
// w2: [head] flat = kh*16384 + term*8192 + nt*512 + kt*64 + lane*2 + reg
// w3:        flat = term*4096 + nt*512 + kt*64 + lane*2 + reg
__device__ __align__(16) uint32_t g_w1f[2][32768];
__device__ __align__(16) uint32_t g_w2f[2][32768];
__device__ __align__(16) uint32_t g_w3f[8192];

// ---------------------------------------------------------------------------
// Helpers
// ---------------------------------------------------------------------------
__device__ __forceinline__ void splitpack(float v0, float v1,
                                          uint32_t& hp, uint32_t& lp) {
    __nv_bfloat16 h0 = __float2bfloat16(v0);
    __nv_bfloat16 h1 = __float2bfloat16(v1);
    float l0 = v0 - __bfloat162float(h0);
    float l1 = v1 - __bfloat162float(h1);
    __nv_bfloat162 hq; hq.x = h0; hq.y = h1;
    __nv_bfloat162 lq; lq.x = __float2bfloat16(l0); lq.y = __float2bfloat16(l1);
    hp = *reinterpret_cast<uint32_t*>(&hq);
    lp = *reinterpret_cast<uint32_t*>(&lq);
}
__device__ __forceinline__ uint32_t pack_hi(float v0, float v1) {
    __nv_bfloat162 q; q.x = __float2bfloat16(v0); q.y = __float2bfloat16(v1);
    return *reinterpret_cast<uint32_t*>(&q);
}
__device__ __forceinline__ uint32_t pack_lo(float v0, float v1) {
    __nv_bfloat16 h0 = __float2bfloat16(v0);
    __nv_bfloat16 h1 = __float2bfloat16(v1);
    __nv_bfloat162 q;
    q.x = __float2bfloat16(v0 - __bfloat162float(h0));
    q.y = __float2bfloat16(v1 - __bfloat162float(h1));
    return *reinterpret_cast<uint32_t*>(&q);
}

// m16n8k16 row.col bf16 -> f32 accumulate
__device__ __forceinline__ void mma_bf16(float* c, const uint32_t* a, uint2 b) {
    asm volatile(
        "mma.sync.aligned.m16n8k16.row.col.f32.bf16.bf16.f32 "
        "{%0,%1,%2,%3}, {%4,%5,%6,%7}, {%8,%9}, {%0,%1,%2,%3};"
        : "+f"(c[0]), "+f"(c[1]), "+f"(c[2]), "+f"(c[3])
        : "r"(a[0]), "r"(a[1]), "r"(a[2]), "r"(a[3]), "r"(b.x), "r"(b.y));
}

// ---------------------------------------------------------------------------
// Small kernels
// ---------------------------------------------------------------------------
__global__ void k_zero() {
    int t = blockIdx.x * blockDim.x + threadIdx.x;
    if (t < B_GRAPHS * D) g_sums[t] = 0.f;
    if (t < B_GRAPHS)     g_cnt[t]  = 0.f;
}

__global__ void k_segsum(const float* __restrict__ re,
                         const int* __restrict__ rb, int R) {
    int idx = blockIdx.x * blockDim.x + threadIdx.x;
    if (idx < R * D) {
        int r = idx >> 7, d = idx & (D - 1);
        atomicAdd(&g_sums[rb[r] * D + d], re[idx]);
    }
    if (idx < R) atomicAdd(&g_cnt[rb[idx]], 1.f);
}

__global__ void k_detect(const unsigned int* __restrict__ w, int nwords) {
    __shared__ int not_int, not_float;
    if (threadIdx.x == 0) { not_int = 0; not_float = 0; }
    __syncthreads();
    int li = 0, lf = 0;
    for (int i = threadIdx.x; i < nwords; i += blockDim.x) {
        unsigned v = w[i];
        if (v > 1u) li = 1;
        if (v != 0u && v != 0x3f800000u) lf = 1;
    }
    if (li) not_int = 1;
    if (lf) not_float = 1;
    __syncthreads();
    if (threadIdx.x == 0) g_mask_kind = not_int ? (not_float ? 0 : 2) : 1;
}

__global__ void k_global(const float* __restrict__ ge_w1, const float* __restrict__ ge_b1,
                         const float* __restrict__ ge_w2, const float* __restrict__ ge_b2,
                         const float* __restrict__ ns_w1, const float* __restrict__ ns_b1,
                         const float* __restrict__ ps_w1, const float* __restrict__ ps_b1) {
    __shared__ float mean[D], h[H1DIM], gc[D];
    int b = blockIdx.x, t = threadIdx.x;
    if (t < D) mean[t] = g_sums[b * D + t] / fmaxf(g_cnt[b], 1.f);
    __syncthreads();
    {
        float a = ge_b1[t];
        #pragma unroll 4
        for (int k = 0; k < D; ++k) a = fmaf(mean[k], ge_w1[k * H1DIM + t], a);
        h[t] = fmaxf(a, 0.f);
    }
    __syncthreads();
    if (t < D) {
        float a = ge_b2[t];
        #pragma unroll 4
        for (int j = 0; j < H1DIM; ++j) a = fmaf(h[j], ge_w2[j * D + t], a);
        gc[t] = a;
    }
    __syncthreads();
    {
        float cn = ns_b1[t], cp = ps_b1[t];
        #pragma unroll 4
        for (int k = 0; k < D; ++k) {
            float g = gc[k];
            cn = fmaf(g, ns_w1[(D + k) * H1DIM + t], cn);
            cp = fmaf(g, ps_w1[(D + k) * H1DIM + t], cp);
        }
        g_contrib_ns[b * H1DIM + t] = cn;
        g_contrib_ps[b * H1DIM + t] = cp;
    }
}

// ---------------------------------------------------------------------------
// B-fragment prep: exact m16n8k16 B register order, bf16 hi/lo split
// ---------------------------------------------------------------------------
__global__ void k_prep(const float* __restrict__ ns_w1, const float* __restrict__ ps_w1,
                       const float* __restrict__ ns_w2, const float* __restrict__ ps_w2,
                       const float* __restrict__ ps_w3) {
    int idx = blockIdx.x * blockDim.x + threadIdx.x;
    if (idx < 65536) {                                  // w1 frags
        int hh = idx >> 15, f = idx & 32767;
        int reg = f & 1, lane = (f >> 1) & 31, kt = (f >> 6) & 7;
        int nt = (f >> 9) & 15, term = (f >> 13) & 1, nh = (f >> 14) & 1;
        int n = nh * 128 + nt * 8 + (lane >> 2);
        int k = kt * 16 + (lane & 3) * 2 + reg * 8;
        const float* w = hh ? ps_w1 : ns_w1;
        float v0 = w[k * H1DIM + n], v1 = w[(k + 1) * H1DIM + n];
        g_w1f[hh][f] = term ? pack_lo(v0, v1) : pack_hi(v0, v1);
    } else if (idx < 131072) {                          // w2 frags
        int j = idx - 65536;
        int hh = j >> 15, f = j & 32767;
        int reg = f & 1, lane = (f >> 1) & 31, kt = (f >> 6) & 7;
        int nt = (f >> 9) & 15, term = (f >> 13) & 1, kh = (f >> 14) & 1;
        int n = nt * 8 + (lane >> 2);
        int k = kh * 128 + kt * 16 + (lane & 3) * 2 + reg * 8;
        const float* w = hh ? ps_w2 : ns_w2;
        float v0 = w[k * H2DIM + n], v1 = w[(k + 1) * H2DIM + n];
        g_w2f[hh][f] = term ? pack_lo(v0, v1) : pack_hi(v0, v1);
    } else if (idx < 131072 + 8192) {                   // w3 (ps) frags
        int f = idx - 131072;
        int reg = f & 1, lane = (f >> 1) & 31, kt = (f >> 6) & 7;
        int nt = (f >> 9) & 7, term = (f >> 12) & 1;
        int n = nt * 8 + (lane >> 2);
        int k = kt * 16 + (lane & 3) * 2 + reg * 8;
        float v0 = ps_w3[k * PNUM + n], v1 = ps_w3[(k + 1) * PNUM + n];
        g_w3f[f] = term ? pack_lo(v0, v1) : pack_hi(v0, v1);
    }
}

// ---------------------------------------------------------------------------
// Fused main kernel: 128 boundary rows/CTA, both heads, HMMA everywhere
// ---------------------------------------------------------------------------
__global__ __launch_bounds__(256, 1) void k_fused(
    const float* __restrict__ node_emb,
    const int*   __restrict__ boundary,
    const int*   __restrict__ nbidx,
    const void*  __restrict__ amask,
    const float* __restrict__ ns_b2, const float* __restrict__ ns_w3,
    const float* __restrict__ ns_b3,
    const float* __restrict__ ps_b2, const float* __restrict__ ps_b3,
    float* __restrict__ out_node, float* __restrict__ out_part, int NB)
{
    extern __shared__ __align__(16) unsigned char smc[];
    uint32_t* Ahi = (uint32_t*)(smc + SM_AHI);
    uint32_t* Alo = (uint32_t*)(smc + SM_ALO);
    uint32_t* Bst = (uint32_t*)(smc + SM_B1);   // B-L1 / B-L3 stage
    uint32_t* B2st = (uint32_t*)(smc);          // B-L2 half stage (over X)
    uint32_t* Hhi = (uint32_t*)(smc + SM_H1HI);
    uint32_t* Hlo = (uint32_t*)(smc + SM_H1LO);
    float* w3ns = (float*)(smc + SM_MISC);
    float* b2ns = w3ns + 128;
    float* b2ps = b2ns + 128;
    float* b3ps = b2ps + 128;
    int* nid_s = (int*)(b3ps + 64);
    int* bid_s = nid_s + 128;

    const int tid = threadIdx.x, wid = tid >> 5, lane = tid & 31;
    const int qid = lane & 3;
    const int r0 = wid * 16 + (lane >> 2);
    const int base = blockIdx.x * 128;

    if (tid < 128) {
        w3ns[tid] = ns_w3[tid];
        b2ns[tid] = ns_b2[tid];
        b2ps[tid] = ps_b2[tid];
        int row = base + tid;
        int rr = row < NB ? row : NB - 1;
        int n = boundary[rr];
        nid_s[tid] = n;
        bid_s[tid] = nbidx[n];
    }
    if (tid < 64) b3ps[tid] = ps_b3[tid];
    __syncthreads();

    for (int head = 0; head < 2; ++head) {
        // ---- gather X rows, split to bf16 hi/lo pair images ----
        for (int r = wid; r < 128; r += 8) {
            float4 v = __ldg((const float4*)(node_emb + (size_t)nid_s[r] * D) + lane);
            uint32_t h0, l0, h1v, l1v;
            splitpack(v.x, v.y, h0, l0);
            splitpack(v.z, v.w, h1v, l1v);
            *(uint2*)(Ahi + r * STRA + 2 * lane) = make_uint2(h0, h1v);
            *(uint2*)(Alo + r * STRA + 2 * lane) = make_uint2(l0, l1v);
        }
        // ---- stage B-L1 (131072 B) ----
        {
            const uint4* s = (const uint4*)g_w1f[head];
            uint4* dd = (uint4*)Bst;
            for (int i = tid; i < 131072 / 16; i += 256) dd[i] = s[i];
        }
        __syncthreads();

        // ================= L1: C[128,256] = X[128,128] @ W1 =================
        float acc[32][4];
        #pragma unroll
        for (int t = 0; t < 32; ++t) {
            acc[t][0] = acc[t][1] = acc[t][2] = acc[t][3] = 0.f;
        }
        for (int kt = 0; kt < 8; ++kt) {
            int kp = kt * 8 + qid;
            uint32_t ah[4], al[4];
            ah[0] = Ahi[r0 * STRA + kp];       ah[1] = Ahi[(r0 + 8) * STRA + kp];
            ah[2] = Ahi[r0 * STRA + kp + 4];   ah[3] = Ahi[(r0 + 8) * STRA + kp + 4];
            al[0] = Alo[r0 * STRA + kp];       al[1] = Alo[(r0 + 8) * STRA + kp];
            al[2] = Alo[r0 * STRA + kp + 4];   al[3] = Alo[(r0 + 8) * STRA + kp + 4];
            #pragma unroll
            for (int nh = 0; nh < 2; ++nh) {
                #pragma unroll
                for (int nt = 0; nt < 16; ++nt) {
                    int bi = nh * 16384 + nt * 512 + kt * 64 + lane * 2;
                    uint2 bh = *(uint2*)(Bst + bi);
                    uint2 bl = *(uint2*)(Bst + bi + 8192);
                    float* c = acc[nh * 16 + nt];
                    mma_bf16(c, ah, bh);
                    mma_bf16(c, al, bh);
                    mma_bf16(c, ah, bl);
                }
            }
        }
        __syncthreads();   // all warps done reading X + B-L1

        // L1 epilogue: +contrib, ReLU, split -> h1 images (over B-L1 region)
        {
            const float* contrib = head ? g_contrib_ps : g_contrib_ns;
            const float* cb0 = contrib + bid_s[r0] * H1DIM;
            const float* cb1 = contrib + bid_s[r0 + 8] * H1DIM;
            #pragma unroll
            for (int nh = 0; nh < 2; ++nh) {
                #pragma unroll
                for (int nt = 0; nt < 16; ++nt) {
                    float* c = acc[nh * 16 + nt];
                    int col = nh * 128 + nt * 8 + qid * 2;
                    int pi = nh * 64 + nt * 4 + qid;
                    float2 q0 = *(const float2*)(cb0 + col);
                    float2 q1 = *(const float2*)(cb1 + col);
                    uint32_t hp, lp;
                    splitpack(fmaxf(c[0] + q0.x, 0.f), fmaxf(c[1] + q0.y, 0.f), hp, lp);
                    Hhi[r0 * STRH + pi] = hp;
                    Hlo[r0 * STRH + pi] = lp;
                    splitpack(fmaxf(c[2] + q1.x, 0.f), fmaxf(c[3] + q1.y, 0.f), hp, lp);
                    Hhi[(r0 + 8) * STRH + pi] = hp;
                    Hlo[(r0 + 8) * STRH + pi] = lp;
                }
            }
        }
        __syncthreads();

        // ================= L2: C[128,128] = h1[128,256] @ W2 =================
        float a2[16][4];
        #pragma unroll
        for (int t = 0; t < 16; ++t) {
            a2[t][0] = a2[t][1] = a2[t][2] = a2[t][3] = 0.f;
        }
        for (int kh = 0; kh < 2; ++kh) {
            {   // stage this k-half of B-L2 (65536 B) over X region
                const uint4* s = (const uint4*)(g_w2f[head] + kh * 16384);
                uint4* dd = (uint4*)B2st;
                for (int i = tid; i < 65536 / 16; i += 256) dd[i] = s[i];
            }
            __syncthreads();
            for (int kt = 0; kt < 8; ++kt) {
                int kp = kh * 64 + kt * 8 + qid;
                uint32_t ah[4], al[4];
                ah[0] = Hhi[r0 * STRH + kp];       ah[1] = Hhi[(r0 + 8) * STRH + kp];
                ah[2] = Hhi[r0 * STRH + kp + 4];   ah[3] = Hhi[(r0 + 8) * STRH + kp + 4];
                al[0] = Hlo[r0 * STRH + kp];       al[1] = Hlo[(r0 + 8) * STRH + kp];
                al[2] = Hlo[r0 * STRH + kp + 4];   al[3] = Hlo[(r0 + 8) * STRH + kp + 4];
                #pragma unroll
                for (int nt = 0; nt < 16; ++nt) {
                    int bi = nt * 512 + kt * 64 + lane * 2;
                    uint2 bh = *(uint2*)(B2st + bi);
                    uint2 bl = *(uint2*)(B2st + bi + 8192);
                    float* c = a2[nt];
                    mma_bf16(c, ah, bh);
                    mma_bf16(c, al, bh);
                    mma_bf16(c, ah, bl);
                }
            }
            __syncthreads();
        }

        if (head == 0) {
            // ---- ns: fused L3 dot (exact fp32) ----
            float d0 = 0.f, d1 = 0.f;
            #pragma unroll
            for (int nt = 0; nt < 16; ++nt) {
                int col = nt * 8 + qid * 2;
                float w0 = w3ns[col], w1v = w3ns[col + 1];
                float bb0 = b2ns[col], bb1 = b2ns[col + 1];
                d0 = fmaf(fmaxf(a2[nt][0] + bb0, 0.f), w0, d0);
                d0 = fmaf(fmaxf(a2[nt][1] + bb1, 0.f), w1v, d0);
                d1 = fmaf(fmaxf(a2[nt][2] + bb0, 0.f), w0, d1);
                d1 = fmaf(fmaxf(a2[nt][3] + bb1, 0.f), w1v, d1);
            }
            d0 += __shfl_xor_sync(0xFFFFFFFFu, d0, 1);
            d0 += __shfl_xor_sync(0xFFFFFFFFu, d0, 2);
            d1 += __shfl_xor_sync(0xFFFFFFFFu, d1, 1);
            d1 += __shfl_xor_sync(0xFFFFFFFFu, d1, 2);
            if (qid == 0) {
                float b3 = ns_b3[0];
                int g0 = base + r0, g1 = base + r0 + 8;
                if (g0 < NB) out_node[g0] = d0 + b3;
                if (g1 < NB) out_node[g1] = d1 + b3;
            }
            __syncthreads();
        } else {
            // ---- ps: h2 -> region0 (B-L2 stage now dead) ----
            uint32_t* H2hi = (uint32_t*)(smc + SM_AHI);
            uint32_t* H2lo = (uint32_t*)(smc + SM_ALO);
            #pragma unroll
            for (int nt = 0; nt < 16; ++nt) {
                int col = nt * 8 + qid * 2;
                int pi = nt * 4 + qid;
                float bb0 = b2ps[col], bb1 = b2ps[col + 1];
                uint32_t hp, lp;
                splitpack(fmaxf(a2[nt][0] + bb0, 0.f), fmaxf(a2[nt][1] + bb1, 0.f), hp, lp);
                H2hi[r0 * STRA + pi] = hp;
                H2lo[r0 * STRA + pi] = lp;
                splitpack(fmaxf(a2[nt][2] + bb0, 0.f), fmaxf(a2[nt][3] + bb1, 0.f), hp, lp);
                H2hi[(r0 + 8) * STRA + pi] = hp;
                H2lo[(r0 + 8) * STRA + pi] = lp;
            }
            // stage B-L3 (32768 B) over h1 region (dead)
            {
                const uint4* s = (const uint4*)g_w3f;
                uint4* dd = (uint4*)Bst;
                for (int i = tid; i < 32768 / 16; i += 256) dd[i] = s[i];
            }
            __syncthreads();

            // ======== L3 ps: C[128,64] = h2[128,128] @ W3 ========
            float a3[8][4];
            #pragma unroll
            for (int t = 0; t < 8; ++t) {
                a3[t][0] = a3[t][1] = a3[t][2] = a3[t][3] = 0.f;
            }
            for (int kt = 0; kt < 8; ++kt) {
                int kp = kt * 8 + qid;
                uint32_t ah[4], al[4];
                ah[0] = H2hi[r0 * STRA + kp];       ah[1] = H2hi[(r0 + 8) * STRA + kp];
                ah[2] = H2hi[r0 * STRA + kp + 4];   ah[3] = H2hi[(r0 + 8) * STRA + kp + 4];
                al[0] = H2lo[r0 * STRA + kp];       al[1] = H2lo[(r0 + 8) * STRA + kp];
                al[2] = H2lo[r0 * STRA + kp + 4];   al[3] = H2lo[(r0 + 8) * STRA + kp + 4];
                #pragma unroll
                for (int nt = 0; nt < 8; ++nt) {
                    int bi = nt * 512 + kt * 64 + lane * 2;
                    uint2 bh = *(uint2*)(Bst + bi);
                    uint2 bl = *(uint2*)(Bst + bi + 4096);
                    float* c = a3[nt];
                    mma_bf16(c, ah, bh);
                    mma_bf16(c, al, bh);
                    mma_bf16(c, ah, bl);
                }
            }

            // L3 epilogue: +b3, mask, store float2
            int kind = g_mask_kind;
            int g0 = base + r0, g1 = base + r0 + 8;
            size_t n0 = (size_t)nid_s[r0] * PNUM;
            size_t n1 = (size_t)nid_s[r0 + 8] * PNUM;
            #pragma unroll
            for (int nt = 0; nt < 8; ++nt) {
                int p = nt * 8 + qid * 2;
                float v0 = a3[nt][0] + b3ps[p];
                float v1 = a3[nt][1] + b3ps[p + 1];
                float v2 = a3[nt][2] + b3ps[p];
                float v3 = a3[nt][3] + b3ps[p + 1];
                bool m0, m1, m2, m3;
                if (kind == 0) {
                    const unsigned char* M = (const unsigned char*)amask;
                    m0 = M[n0 + p]; m1 = M[n0 + p + 1];
                    m2 = M[n1 + p]; m3 = M[n1 + p + 1];
                } else if (kind == 1) {
                    const int* M = (const int*)amask;
                    m0 = M[n0 + p] != 0; m1 = M[n0 + p + 1] != 0;
                    m2 = M[n1 + p] != 0; m3 = M[n1 + p + 1] != 0;
                } else {
                    const float* M = (const float*)amask;
                    m0 = M[n0 + p] != 0.f; m1 = M[n0 + p + 1] != 0.f;
                    m2 = M[n1 + p] != 0.f; m3 = M[n1 + p + 1] != 0.f;
                }
                if (g0 < NB)
                    *(float2*)(out_part + (size_t)g0 * PNUM + p) =
                        make_float2(m0 ? v0 : -1e9f, m1 ? v1 : -1e9f);
                if (g1 < NB)
                    *(float2*)(out_part + (size_t)g1 * PNUM + p) =
                        make_float2(m2 ? v2 : -1e9f, m3 ? v3 : -1e9f);
            }
        }
    }
}

// ---------------------------------------------------------------------------
// Launcher
// ---------------------------------------------------------------------------
extern "C" void kernel_launch(void* const* d_in, const int* in_sizes, int n_in,
                              void* d_out, int out_size) {
    const float* node_emb   = (const float*)d_in[0];
    const float* region_emb = (const float*)d_in[1];
    const int*   boundary   = (const int*)d_in[2];
    const int*   nbidx      = (const int*)d_in[3];
    const int*   rbidx      = (const int*)d_in[4];
    const void*  amask      = d_in[5];
    const float* ge_w1 = (const float*)d_in[6];
    const float* ge_b1 = (const float*)d_in[7];
    const float* ge_w2 = (const float*)d_in[8];
    const float* ge_b2 = (const float*)d_in[9];
    const float* ns_w1 = (const float*)d_in[10];
    const float* ns_b1 = (const float*)d_in[11];
    const float* ns_w2 = (const float*)d_in[12];
    const float* ns_b2 = (const float*)d_in[13];
    const float* ns_w3 = (const float*)d_in[14];
    const float* ns_b3 = (const float*)d_in[15];
    const float* ps_w1 = (const float*)d_in[16];
    const float* ps_b1 = (const float*)d_in[17];
    const float* ps_w2 = (const float*)d_in[18];
    const float* ps_b2 = (const float*)d_in[19];
    const float* ps_w3 = (const float*)d_in[20];
    const float* ps_b3 = (const float*)d_in[21];

    const int NB = in_sizes[2];
    const int R  = in_sizes[4];
    const int maskElems = in_sizes[5];

    float* out_node = (float*)d_out;
    float* out_part = out_node + NB;

    cudaFuncSetAttribute(k_fused, cudaFuncAttributeMaxDynamicSharedMemorySize,
                         SMEM_BYTES);

    k_zero<<<(B_GRAPHS * D + 255) / 256, 256>>>();
    k_segsum<<<(R * D + 255) / 256, 256>>>(region_emb, rbidx, R);

    int nwords = maskElems / 4;
    if (nwords > 65536) nwords = 65536;
    k_detect<<<1, 256>>>((const unsigned int*)amask, nwords);

    k_prep<<<(139264 + 255) / 256, 256>>>(ns_w1, ps_w1, ns_w2, ps_w2, ps_w3);
    k_global<<<B_GRAPHS, 256>>>(ge_w1, ge_b1, ge_w2, ge_b2,
                                ns_w1, ns_b1, ps_w1, ps_b1);

    int grid = (NB + 127) / 128;
    k_fused<<<grid, 256, SMEM_BYTES>>>(node_emb, boundary, nbidx, amask,
                                       ns_b2, ns_w3, ns_b3, ps_b2, ps_b3,
                                       out_node, out_part, NB);
}

// round 17
// speedup vs baseline: 2.9163x; 1.1561x over previous
#include <cuda_runtime.h>
#include <cuda_bf16.h>
#include <cstdint>

// ---------------------------------------------------------------------------
// Problem constants
// ---------------------------------------------------------------------------
#define B_GRAPHS 64
#define D 128
#define H1DIM 256
#define H2DIM 128
#define PNUM 64

// SMEM byte offsets (dynamic smem)
#define SM_AHI 0          // X / h2 hi pairs: [128][68] uint32 = 34816 B
#define SM_ALO 34816      // X / h2 lo pairs
#define SM_B1  69632      // B-L1 stage (131072 B) / h1 / B-L3
#define SM_H1HI 69632     // h1 hi pairs: [128][132] uint32 = 67584 B
#define SM_H1LO 137216    // h1 lo pairs
#define SM_MISC 204800
#define SMEM_BYTES 208640
#define STRA 68           // uint32 stride for K=128 pair images
#define STRH 132          // uint32 stride for K=256 pair images

// ---------------------------------------------------------------------------
// Device scratch
// ---------------------------------------------------------------------------
__device__ float g_sums[B_GRAPHS * D];
__device__ float g_cnt[B_GRAPHS];
__device__ float g_gc[B_GRAPHS * D];
__device__ float g_contrib_ns[B_GRAPHS * H1DIM];
__device__ float g_contrib_ps[B_GRAPHS * H1DIM];
__device__ int   g_mask_kind;

// Pre-built B fragments in m16n8k16 register order (bf16x2 per uint32).
__device__ __align__(16) uint32_t g_w1f[2][32768];
__device__ __align__(16) uint32_t g_w2f[2][32768];
__device__ __align__(16) uint32_t g_w3f[8192];

// ---------------------------------------------------------------------------
// Helpers
// ---------------------------------------------------------------------------
__device__ __forceinline__ void splitpack(float v0, float v1,
                                          uint32_t& hp, uint32_t& lp) {
    __nv_bfloat16 h0 = __float2bfloat16(v0);
    __nv_bfloat16 h1 = __float2bfloat16(v1);
    float l0 = v0 - __bfloat162float(h0);
    float l1 = v1 - __bfloat162float(h1);
    __nv_bfloat162 hq; hq.x = h0; hq.y = h1;
    __nv_bfloat162 lq; lq.x = __float2bfloat16(l0); lq.y = __float2bfloat16(l1);
    hp = *reinterpret_cast<uint32_t*>(&hq);
    lp = *reinterpret_cast<uint32_t*>(&lq);
}
__device__ __forceinline__ uint32_t pack_hi(float v0, float v1) {
    __nv_bfloat162 q; q.x = __float2bfloat16(v0); q.y = __float2bfloat16(v1);
    return *reinterpret_cast<uint32_t*>(&q);
}
__device__ __forceinline__ uint32_t pack_lo(float v0, float v1) {
    __nv_bfloat16 h0 = __float2bfloat16(v0);
    __nv_bfloat16 h1 = __float2bfloat16(v1);
    __nv_bfloat162 q;
    q.x = __float2bfloat16(v0 - __bfloat162float(h0));
    q.y = __float2bfloat16(v1 - __bfloat162float(h1));
    return *reinterpret_cast<uint32_t*>(&q);
}

__device__ __forceinline__ void mma_bf16(float* c, const uint32_t* a, uint2 b) {
    asm volatile(
        "mma.sync.aligned.m16n8k16.row.col.f32.bf16.bf16.f32 "
        "{%0,%1,%2,%3}, {%4,%5,%6,%7}, {%8,%9}, {%0,%1,%2,%3};"
        : "+f"(c[0]), "+f"(c[1]), "+f"(c[2]), "+f"(c[3])
        : "r"(a[0]), "r"(a[1]), "r"(a[2]), "r"(a[3]), "r"(b.x), "r"(b.y));
}

// ---------------------------------------------------------------------------
// Small kernels
// ---------------------------------------------------------------------------
__global__ void k_zero() {
    int t = blockIdx.x * blockDim.x + threadIdx.x;
    if (t < B_GRAPHS * D) g_sums[t] = 0.f;
    if (t < B_GRAPHS)     g_cnt[t]  = 0.f;
}

__global__ void k_segsum(const float* __restrict__ re,
                         const int* __restrict__ rb, int R) {
    int idx = blockIdx.x * blockDim.x + threadIdx.x;
    if (idx < R * D) {
        int r = idx >> 7, d = idx & (D - 1);
        atomicAdd(&g_sums[rb[r] * D + d], re[idx]);
    }
    if (idx < R) atomicAdd(&g_cnt[rb[idx]], 1.f);
}

__global__ void k_detect(const unsigned int* __restrict__ w, int nwords) {
    __shared__ int not_int, not_float;
    if (threadIdx.x == 0) { not_int = 0; not_float = 0; }
    __syncthreads();
    int li = 0, lf = 0;
    for (int i = threadIdx.x; i < nwords; i += blockDim.x) {
        unsigned v = w[i];
        if (v > 1u) li = 1;
        if (v != 0u && v != 0x3f800000u) lf = 1;
    }
    if (li) not_int = 1;
    if (lf) not_float = 1;
    __syncthreads();
    if (threadIdx.x == 0) g_mask_kind = not_int ? (not_float ? 0 : 2) : 1;
}

// gc = relu(mean@ge_w1+b1)@ge_w2+b2    (one block per batch)
__global__ void k_gc(const float* __restrict__ ge_w1, const float* __restrict__ ge_b1,
                     const float* __restrict__ ge_w2, const float* __restrict__ ge_b2) {
    __shared__ float mean[D], h[H1DIM];
    int b = blockIdx.x, t = threadIdx.x;
    if (t < D) mean[t] = g_sums[b * D + t] / fmaxf(g_cnt[b], 1.f);
    __syncthreads();
    {
        float a = ge_b1[t];
        #pragma unroll 8
        for (int k = 0; k < D; ++k) a = fmaf(mean[k], ge_w1[k * H1DIM + t], a);
        h[t] = fmaxf(a, 0.f);
    }
    __syncthreads();
    if (t < D) {
        float a = ge_b2[t];
        #pragma unroll 8
        for (int j = 0; j < H1DIM; ++j) a = fmaf(h[j], ge_w2[j * D + t], a);
        g_gc[b * D + t] = a;
    }
}

// contrib[b][t] = sum_k gc[b][k]*w1[128+k][t] + b1[t]  (blockIdx.x = b + 64*head)
__global__ void k_contrib(const float* __restrict__ ns_w1, const float* __restrict__ ns_b1,
                          const float* __restrict__ ps_w1, const float* __restrict__ ps_b1) {
    __shared__ float gc[D];
    int b = blockIdx.x & 63, head = blockIdx.x >> 6, t = threadIdx.x;
    if (t < D) gc[t] = g_gc[b * D + t];
    __syncthreads();
    const float* w1 = head ? ps_w1 : ns_w1;
    const float* b1 = head ? ps_b1 : ns_b1;
    float* dst = head ? g_contrib_ps : g_contrib_ns;
    float a = b1[t];
    #pragma unroll 8
    for (int k = 0; k < D; ++k) a = fmaf(gc[k], w1[(D + k) * H1DIM + t], a);
    dst[b * H1DIM + t] = a;
}

// ---------------------------------------------------------------------------
// B-fragment prep: exact m16n8k16 B register order, bf16 hi/lo split
// ---------------------------------------------------------------------------
__global__ void k_prep(const float* __restrict__ ns_w1, const float* __restrict__ ps_w1,
                       const float* __restrict__ ns_w2, const float* __restrict__ ps_w2,
                       const float* __restrict__ ps_w3) {
    int idx = blockIdx.x * blockDim.x + threadIdx.x;
    if (idx < 65536) {                                  // w1 frags
        int hh = idx >> 15, f = idx & 32767;
        int reg = f & 1, lane = (f >> 1) & 31, kt = (f >> 6) & 7;
        int nt = (f >> 9) & 15, term = (f >> 13) & 1, nh = (f >> 14) & 1;
        int n = nh * 128 + nt * 8 + (lane >> 2);
        int k = kt * 16 + (lane & 3) * 2 + reg * 8;
        const float* w = hh ? ps_w1 : ns_w1;
        float v0 = w[k * H1DIM + n], v1 = w[(k + 1) * H1DIM + n];
        g_w1f[hh][f] = term ? pack_lo(v0, v1) : pack_hi(v0, v1);
    } else if (idx < 131072) {                          // w2 frags
        int j = idx - 65536;
        int hh = j >> 15, f = j & 32767;
        int reg = f & 1, lane = (f >> 1) & 31, kt = (f >> 6) & 7;
        int nt = (f >> 9) & 15, term = (f >> 13) & 1, kh = (f >> 14) & 1;
        int n = nt * 8 + (lane >> 2);
        int k = kh * 128 + kt * 16 + (lane & 3) * 2 + reg * 8;
        const float* w = hh ? ps_w2 : ns_w2;
        float v0 = w[k * H2DIM + n], v1 = w[(k + 1) * H2DIM + n];
        g_w2f[hh][f] = term ? pack_lo(v0, v1) : pack_hi(v0, v1);
    } else if (idx < 131072 + 8192) {                   // w3 (ps) frags
        int f = idx - 131072;
        int reg = f & 1, lane = (f >> 1) & 31, kt = (f >> 6) & 7;
        int nt = (f >> 9) & 7, term = (f >> 12) & 1;
        int n = nt * 8 + (lane >> 2);
        int k = kt * 16 + (lane & 3) * 2 + reg * 8;
        float v0 = ps_w3[k * PNUM + n], v1 = ps_w3[(k + 1) * PNUM + n];
        g_w3f[f] = term ? pack_lo(v0, v1) : pack_hi(v0, v1);
    }
}

// ---------------------------------------------------------------------------
// Fused main kernel: 128 rows/CTA, 512 threads / 16 warps.
// Warp pair (w, w+8) shares a 16-row stripe; nhalf = wid>>3 selects the
// output-column half. Same smem layout as the 256-thread version.
// ---------------------------------------------------------------------------
__global__ __launch_bounds__(512, 1) void k_fused(
    const float* __restrict__ node_emb,
    const int*   __restrict__ boundary,
    const int*   __restrict__ nbidx,
    const void*  __restrict__ amask,
    const float* __restrict__ ns_b2, const float* __restrict__ ns_w3,
    const float* __restrict__ ns_b3,
    const float* __restrict__ ps_b2, const float* __restrict__ ps_b3,
    float* __restrict__ out_node, float* __restrict__ out_part, int NB)
{
    extern __shared__ __align__(16) unsigned char smc[];
    uint32_t* Ahi = (uint32_t*)(smc + SM_AHI);
    uint32_t* Alo = (uint32_t*)(smc + SM_ALO);
    uint32_t* Bst = (uint32_t*)(smc + SM_B1);   // B-L1 / B-L3 stage
    uint32_t* B2st = (uint32_t*)(smc);          // B-L2 half stage (over X)
    uint32_t* Hhi = (uint32_t*)(smc + SM_H1HI);
    uint32_t* Hlo = (uint32_t*)(smc + SM_H1LO);
    float* w3ns = (float*)(smc + SM_MISC);
    float* b2ns = w3ns + 128;
    float* b2ps = b2ns + 128;
    float* b3ps = b2ps + 128;
    float* part = b3ps + 64;          // [128] cross-warp dot partials
    int* nid_s = (int*)(part + 128);
    int* bid_s = nid_s + 128;

    const int tid = threadIdx.x, wid = tid >> 5, lane = tid & 31;
    const int qid = lane & 3;
    const int rw = wid & 7;           // row-stripe
    const int nhalf = wid >> 3;       // output-column half
    const int r0 = rw * 16 + (lane >> 2);
    const int base = blockIdx.x * 128;

    if (tid < 128) {
        w3ns[tid] = ns_w3[tid];
        b2ns[tid] = ns_b2[tid];
        b2ps[tid] = ps_b2[tid];
        int row = base + tid;
        int rr = row < NB ? row : NB - 1;
        int n = boundary[rr];
        nid_s[tid] = n;
        bid_s[tid] = nbidx[n];
    }
    if (tid >= 128 && tid < 192) b3ps[tid - 128] = ps_b3[tid - 128];
    __syncthreads();

    for (int head = 0; head < 2; ++head) {
        // ---- gather X rows (8 per warp), split to bf16 hi/lo pair images ----
        for (int r = wid; r < 128; r += 16) {
            float4 v = __ldg((const float4*)(node_emb + (size_t)nid_s[r] * D) + lane);
            uint32_t h0, l0, h1v, l1v;
            splitpack(v.x, v.y, h0, l0);
            splitpack(v.z, v.w, h1v, l1v);
            *(uint2*)(Ahi + r * STRA + 2 * lane) = make_uint2(h0, h1v);
            *(uint2*)(Alo + r * STRA + 2 * lane) = make_uint2(l0, l1v);
        }
        // ---- stage B-L1 (131072 B) ----
        {
            const uint4* s = (const uint4*)g_w1f[head];
            uint4* dd = (uint4*)Bst;
            for (int i = tid; i < 131072 / 16; i += 512) dd[i] = s[i];
        }
        __syncthreads();

        // ========= L1: C[128, nh-half of 256] = X[128,128] @ W1 =========
        float acc[16][4];
        #pragma unroll
        for (int t = 0; t < 16; ++t) {
            acc[t][0] = acc[t][1] = acc[t][2] = acc[t][3] = 0.f;
        }
        for (int kt = 0; kt < 8; ++kt) {
            int kp = kt * 8 + qid;
            uint32_t ah[4], al[4];
            ah[0] = Ahi[r0 * STRA + kp];       ah[1] = Ahi[(r0 + 8) * STRA + kp];
            ah[2] = Ahi[r0 * STRA + kp + 4];   ah[3] = Ahi[(r0 + 8) * STRA + kp + 4];
            al[0] = Alo[r0 * STRA + kp];       al[1] = Alo[(r0 + 8) * STRA + kp];
            al[2] = Alo[r0 * STRA + kp + 4];   al[3] = Alo[(r0 + 8) * STRA + kp + 4];
            #pragma unroll
            for (int nt = 0; nt < 16; ++nt) {
                int bi = nhalf * 16384 + nt * 512 + kt * 64 + lane * 2;
                uint2 bh = *(uint2*)(Bst + bi);
                uint2 bl = *(uint2*)(Bst + bi + 8192);
                float* c = acc[nt];
                mma_bf16(c, ah, bh);
                mma_bf16(c, al, bh);
                mma_bf16(c, ah, bl);
            }
        }
        __syncthreads();   // all warps done reading X + B-L1

        // L1 epilogue: +contrib, ReLU, split -> h1 images (over B-L1 region)
        {
            const float* contrib = head ? g_contrib_ps : g_contrib_ns;
            const float* cb0 = contrib + bid_s[r0] * H1DIM;
            const float* cb1 = contrib + bid_s[r0 + 8] * H1DIM;
            #pragma unroll
            for (int nt = 0; nt < 16; ++nt) {
                float* c = acc[nt];
                int col = nhalf * 128 + nt * 8 + qid * 2;
                int pi = nhalf * 64 + nt * 4 + qid;
                float2 q0 = *(const float2*)(cb0 + col);
                float2 q1 = *(const float2*)(cb1 + col);
                uint32_t hp, lp;
                splitpack(fmaxf(c[0] + q0.x, 0.f), fmaxf(c[1] + q0.y, 0.f), hp, lp);
                Hhi[r0 * STRH + pi] = hp;
                Hlo[r0 * STRH + pi] = lp;
                splitpack(fmaxf(c[2] + q1.x, 0.f), fmaxf(c[3] + q1.y, 0.f), hp, lp);
                Hhi[(r0 + 8) * STRH + pi] = hp;
                Hlo[(r0 + 8) * STRH + pi] = lp;
            }
        }
        __syncthreads();

        // ========= L2: C[128, nhalf-half of 128] = h1[128,256] @ W2 =========
        float a2[8][4];
        #pragma unroll
        for (int t = 0; t < 8; ++t) {
            a2[t][0] = a2[t][1] = a2[t][2] = a2[t][3] = 0.f;
        }
        for (int kh = 0; kh < 2; ++kh) {
            {   // stage this k-half of B-L2 (65536 B) over X region
                const uint4* s = (const uint4*)(g_w2f[head] + kh * 16384);
                uint4* dd = (uint4*)B2st;
                for (int i = tid; i < 65536 / 16; i += 512) dd[i] = s[i];
            }
            __syncthreads();
            for (int kt = 0; kt < 8; ++kt) {
                int kp = kh * 64 + kt * 8 + qid;
                uint32_t ah[4], al[4];
                ah[0] = Hhi[r0 * STRH + kp];       ah[1] = Hhi[(r0 + 8) * STRH + kp];
                ah[2] = Hhi[r0 * STRH + kp + 4];   ah[3] = Hhi[(r0 + 8) * STRH + kp + 4];
                al[0] = Hlo[r0 * STRH + kp];       al[1] = Hlo[(r0 + 8) * STRH + kp];
                al[2] = Hlo[r0 * STRH + kp + 4];   al[3] = Hlo[(r0 + 8) * STRH + kp + 4];
                #pragma unroll
                for (int nt = 0; nt < 8; ++nt) {
                    int ntg = nhalf * 8 + nt;
                    int bi = ntg * 512 + kt * 64 + lane * 2;
                    uint2 bh = *(uint2*)(B2st + bi);
                    uint2 bl = *(uint2*)(B2st + bi + 8192);
                    float* c = a2[nt];
                    mma_bf16(c, ah, bh);
                    mma_bf16(c, al, bh);
                    mma_bf16(c, ah, bl);
                }
            }
            __syncthreads();
        }

        if (head == 0) {
            // ---- ns: fused L3 partial dot over this warp's 64 cols ----
            float d0 = 0.f, d1 = 0.f;
            #pragma unroll
            for (int nt = 0; nt < 8; ++nt) {
                int col = (nhalf * 8 + nt) * 8 + qid * 2;
                float w0 = w3ns[col], w1v = w3ns[col + 1];
                float bb0 = b2ns[col], bb1 = b2ns[col + 1];
                d0 = fmaf(fmaxf(a2[nt][0] + bb0, 0.f), w0, d0);
                d0 = fmaf(fmaxf(a2[nt][1] + bb1, 0.f), w1v, d0);
                d1 = fmaf(fmaxf(a2[nt][2] + bb0, 0.f), w0, d1);
                d1 = fmaf(fmaxf(a2[nt][3] + bb1, 0.f), w1v, d1);
            }
            d0 += __shfl_xor_sync(0xFFFFFFFFu, d0, 1);
            d0 += __shfl_xor_sync(0xFFFFFFFFu, d0, 2);
            d1 += __shfl_xor_sync(0xFFFFFFFFu, d1, 1);
            d1 += __shfl_xor_sync(0xFFFFFFFFu, d1, 2);
            if (nhalf == 0 && qid == 0) {
                part[r0] = d0;
                part[r0 + 8] = d1;
            }
            __syncthreads();
            if (nhalf == 1 && qid == 0) {
                float b3 = ns_b3[0];
                int g0 = base + r0, g1 = base + r0 + 8;
                if (g0 < NB) out_node[g0] = part[r0] + d0 + b3;
                if (g1 < NB) out_node[g1] = part[r0 + 8] + d1 + b3;
            }
            __syncthreads();
        } else {
            // ---- ps: h2 -> region0 (B-L2 stage now dead) ----
            uint32_t* H2hi = (uint32_t*)(smc + SM_AHI);
            uint32_t* H2lo = (uint32_t*)(smc + SM_ALO);
            #pragma unroll
            for (int nt = 0; nt < 8; ++nt) {
                int ntg = nhalf * 8 + nt;
                int col = ntg * 8 + qid * 2;
                int pi = ntg * 4 + qid;
                float bb0 = b2ps[col], bb1 = b2ps[col + 1];
                uint32_t hp, lp;
                splitpack(fmaxf(a2[nt][0] + bb0, 0.f), fmaxf(a2[nt][1] + bb1, 0.f), hp, lp);
                H2hi[r0 * STRA + pi] = hp;
                H2lo[r0 * STRA + pi] = lp;
                splitpack(fmaxf(a2[nt][2] + bb0, 0.f), fmaxf(a2[nt][3] + bb1, 0.f), hp, lp);
                H2hi[(r0 + 8) * STRA + pi] = hp;
                H2lo[(r0 + 8) * STRA + pi] = lp;
            }
            // stage B-L3 (32768 B) over h1 region (dead)
            {
                const uint4* s = (const uint4*)g_w3f;
                uint4* dd = (uint4*)Bst;
                for (int i = tid; i < 32768 / 16; i += 512) dd[i] = s[i];
            }
            __syncthreads();

            // ======== L3 ps: C[128, nhalf-half of 64] = h2 @ W3 ========
            float a3[4][4];
            #pragma unroll
            for (int t = 0; t < 4; ++t) {
                a3[t][0] = a3[t][1] = a3[t][2] = a3[t][3] = 0.f;
            }
            for (int kt = 0; kt < 8; ++kt) {
                int kp = kt * 8 + qid;
                uint32_t ah[4], al[4];
                ah[0] = H2hi[r0 * STRA + kp];       ah[1] = H2hi[(r0 + 8) * STRA + kp];
                ah[2] = H2hi[r0 * STRA + kp + 4];   ah[3] = H2hi[(r0 + 8) * STRA + kp + 4];
                al[0] = H2lo[r0 * STRA + kp];       al[1] = H2lo[(r0 + 8) * STRA + kp];
                al[2] = H2lo[r0 * STRA + kp + 4];   al[3] = H2lo[(r0 + 8) * STRA + kp + 4];
                #pragma unroll
                for (int nt = 0; nt < 4; ++nt) {
                    int ntg = nhalf * 4 + nt;
                    int bi = ntg * 512 + kt * 64 + lane * 2;
                    uint2 bh = *(uint2*)(Bst + bi);
                    uint2 bl = *(uint2*)(Bst + bi + 4096);
                    float* c = a3[nt];
                    mma_bf16(c, ah, bh);
                    mma_bf16(c, al, bh);
                    mma_bf16(c, ah, bl);
                }
            }

            // L3 epilogue: +b3, mask, store float2
            int kind = g_mask_kind;
            int g0 = base + r0, g1 = base + r0 + 8;
            size_t n0 = (size_t)nid_s[r0] * PNUM;
            size_t n1 = (size_t)nid_s[r0 + 8] * PNUM;
            #pragma unroll
            for (int nt = 0; nt < 4; ++nt) {
                int p = (nhalf * 4 + nt) * 8 + qid * 2;
                float v0 = a3[nt][0] + b3ps[p];
                float v1 = a3[nt][1] + b3ps[p + 1];
                float v2 = a3[nt][2] + b3ps[p];
                float v3 = a3[nt][3] + b3ps[p + 1];
                bool m0, m1, m2, m3;
                if (kind == 0) {
                    const unsigned char* M = (const unsigned char*)amask;
                    m0 = M[n0 + p]; m1 = M[n0 + p + 1];
                    m2 = M[n1 + p]; m3 = M[n1 + p + 1];
                } else if (kind == 1) {
                    const int* M = (const int*)amask;
                    m0 = M[n0 + p] != 0; m1 = M[n0 + p + 1] != 0;
                    m2 = M[n1 + p] != 0; m3 = M[n1 + p + 1] != 0;
                } else {
                    const float* M = (const float*)amask;
                    m0 = M[n0 + p] != 0.f; m1 = M[n0 + p + 1] != 0.f;
                    m2 = M[n1 + p] != 0.f; m3 = M[n1 + p + 1] != 0.f;
                }
                if (g0 < NB)
                    *(float2*)(out_part + (size_t)g0 * PNUM + p) =
                        make_float2(m0 ? v0 : -1e9f, m1 ? v1 : -1e9f);
                if (g1 < NB)
                    *(float2*)(out_part + (size_t)g1 * PNUM + p) =
                        make_float2(m2 ? v2 : -1e9f, m3 ? v3 : -1e9f);
            }
        }
    }
}

// ---------------------------------------------------------------------------
// Launcher
// ---------------------------------------------------------------------------
extern "C" void kernel_launch(void* const* d_in, const int* in_sizes, int n_in,
                              void* d_out, int out_size) {
    const float* node_emb   = (const float*)d_in[0];
    const float* region_emb = (const float*)d_in[1];
    const int*   boundary   = (const int*)d_in[2];
    const int*   nbidx      = (const int*)d_in[3];
    const int*   rbidx      = (const int*)d_in[4];
    const void*  amask      = d_in[5];
    const float* ge_w1 = (const float*)d_in[6];
    const float* ge_b1 = (const float*)d_in[7];
    const float* ge_w2 = (const float*)d_in[8];
    const float* ge_b2 = (const float*)d_in[9];
    const float* ns_w1 = (const float*)d_in[10];
    const float* ns_b1 = (const float*)d_in[11];
    const float* ns_w2 = (const float*)d_in[12];
    const float* ns_b2 = (const float*)d_in[13];
    const float* ns_w3 = (const float*)d_in[14];
    const float* ns_b3 = (const float*)d_in[15];
    const float* ps_w1 = (const float*)d_in[16];
    const float* ps_b1 = (const float*)d_in[17];
    const float* ps_w2 = (const float*)d_in[18];
    const float* ps_b2 = (const float*)d_in[19];
    const float* ps_w3 = (const float*)d_in[20];
    const float* ps_b3 = (const float*)d_in[21];

    const int NB = in_sizes[2];
    const int R  = in_sizes[4];
    const int maskElems = in_sizes[5];

    float* out_node = (float*)d_out;
    float* out_part = out_node + NB;

    cudaFuncSetAttribute(k_fused, cudaFuncAttributeMaxDynamicSharedMemorySize,
                         SMEM_BYTES);

    k_zero<<<(B_GRAPHS * D + 255) / 256, 256>>>();
    k_segsum<<<(R * D + 255) / 256, 256>>>(region_emb, rbidx, R);

    int nwords = maskElems / 4;
    if (nwords > 65536) nwords = 65536;
    k_detect<<<1, 256>>>((const unsigned int*)amask, nwords);

    k_prep<<<(139264 + 255) / 256, 256>>>(ns_w1, ps_w1, ns_w2, ps_w2, ps_w3);
    k_gc<<<B_GRAPHS, 256>>>(ge_w1, ge_b1, ge_w2, ge_b2);
    k_contrib<<<2 * B_GRAPHS, 256>>>(ns_w1, ns_b1, ps_w1, ps_b1);

    int grid = (NB + 127) / 128;
    k_fused<<<grid, 512, SMEM_BYTES>>>(node_emb, boundary, nbidx, amask,
                                       ns_b2, ns_w3, ns_b3, ps_b2, ps_b3,
                                       out_node, out_part, NB);
}